// round 11
// baseline (speedup 1.0000x reference)
#include <cuda_runtime.h>
#include <cstddef>

// Problem constants
#define BB 16      // batch
#define TT 2048    // text len
#define EE 768     // embed dim
#define E4 (EE/4)  // 192 float4 per row
#define SS 32      // num sentences
#define LL 64      // max sent len
#define NT 128     // t-chunks per batch for pooling pass
#define TCH (TT / NT)   // 16 timesteps per chunk
#define JC 8       // rows (j) per gather block
#define GB 4       // batches per pipeline group (25MB in + 25MB out << 126MB L2)

// Scratch (no device allocation allowed -> __device__ globals)
__device__ float4 g_partial4[BB * NT * E4];  // 6.3MB partial sums (b, chunk, e4)
__device__ int    g_start[BB * SS];
__device__ int    g_len[BB * SS];

// ---------------------------------------------------------------------------
// Kernel 1: streaming partial mean-pool for one group of GB batches.
// grid = GB*NT = 512 blocks, 192 threads; thread owns one float4 column.
// TCH=16: 16 independent LDG.128 per thread, 4 accumulators (4-deep chains).
// Side effect we rely on: leaves this group's input resident in L2.
// ---------------------------------------------------------------------------
__global__ __launch_bounds__(192) void k_pool(const float4* __restrict__ in,
                                              int b0) {
    const int blk = blockIdx.x;
    const int b = b0 + (blk >> 7);   // / NT
    const int c = blk & (NT - 1);    // % NT
    const int e4 = threadIdx.x;      // 0..191

    const float4* base = in + ((size_t)b * TT + (size_t)c * TCH) * E4 + e4;

    float4 a0 = make_float4(0.f, 0.f, 0.f, 0.f);
    float4 a1 = make_float4(0.f, 0.f, 0.f, 0.f);
    float4 a2 = make_float4(0.f, 0.f, 0.f, 0.f);
    float4 a3 = make_float4(0.f, 0.f, 0.f, 0.f);
#pragma unroll
    for (int t = 0; t < TCH; t += 4) {
        float4 v0 = base[(size_t)(t + 0) * E4];
        float4 v1 = base[(size_t)(t + 1) * E4];
        float4 v2 = base[(size_t)(t + 2) * E4];
        float4 v3 = base[(size_t)(t + 3) * E4];
        a0.x += v0.x; a0.y += v0.y; a0.z += v0.z; a0.w += v0.w;
        a1.x += v1.x; a1.y += v1.y; a1.z += v1.z; a1.w += v1.w;
        a2.x += v2.x; a2.y += v2.y; a2.z += v2.z; a2.w += v2.w;
        a3.x += v3.x; a3.y += v3.y; a3.z += v3.z; a3.w += v3.w;
    }
    float4 s;
    s.x = (a0.x + a1.x) + (a2.x + a3.x);
    s.y = (a0.y + a1.y) + (a2.y + a3.y);
    s.z = (a0.z + a1.z) + (a2.z + a3.z);
    s.w = (a0.w + a1.w) + (a2.w + a3.w);
    g_partial4[(size_t)(b * NT + c) * E4 + e4] = s;
}

// ---------------------------------------------------------------------------
// Kernel 2: finish mean + tiny GEMV + exact index math (matches reference):
//   start_off = (int)clip(off_s, 0, 63); end_off = (int)clip(off_{s+32},0,63)
//   start = clip(s*64+start_off, 0, T-L); end = clip(s*64+64+end_off, start, T)
// grid = GB blocks, 512 threads.
// ---------------------------------------------------------------------------
__global__ __launch_bounds__(512) void k_idx(const float* __restrict__ W,
                                             const float* __restrict__ bias,
                                             int b0) {
    const int b = b0 + blockIdx.x;
    const int tid = threadIdx.x;
    __shared__ float pooled[EE];
    __shared__ float4 pA[2 * E4];
    __shared__ float red[8][2 * SS];

    if (tid < 2 * E4) {
        const int g = tid / E4;          // 0..1 (chunk half)
        const int e4 = tid - g * E4;     // 0..191
        const float4* p = g_partial4 + ((size_t)b * NT + (size_t)g * (NT / 2)) * E4 + e4;
        float4 a0 = make_float4(0.f, 0.f, 0.f, 0.f);
        float4 a1 = make_float4(0.f, 0.f, 0.f, 0.f);
#pragma unroll 8
        for (int c = 0; c < NT / 2; c += 2) {
            float4 v0 = p[(size_t)c * E4];
            float4 v1 = p[(size_t)(c + 1) * E4];
            a0.x += v0.x; a0.y += v0.y; a0.z += v0.z; a0.w += v0.w;
            a1.x += v1.x; a1.y += v1.y; a1.z += v1.z; a1.w += v1.w;
        }
        float4 s;
        s.x = a0.x + a1.x; s.y = a0.y + a1.y; s.z = a0.z + a1.z; s.w = a0.w + a1.w;
        pA[tid] = s;
    }
    __syncthreads();
    if (tid < E4) {
        const float inv = 1.0f / (float)TT;
        float4 u = pA[tid], w = pA[E4 + tid];
        pooled[4 * tid + 0] = (u.x + w.x) * inv;
        pooled[4 * tid + 1] = (u.y + w.y) * inv;
        pooled[4 * tid + 2] = (u.z + w.z) * inv;
        pooled[4 * tid + 3] = (u.w + w.w) * inv;
    }
    __syncthreads();

    // col = tid & 63, segment g = tid >> 6 (0..7), 96 elems each.
    {
        const int col = tid & (2 * SS - 1);
        const int g = tid >> 6;
        float acc = 0.f;
        const int e0 = g * 96;
#pragma unroll 8
        for (int e = e0; e < e0 + 96; e++)
            acc = fmaf(pooled[e], W[e * (2 * SS) + col], acc);
        red[g][col] = acc;
    }
    __syncthreads();

    if (tid < SS) {
        const int s = tid;
        float off1 = bias[s], off2 = bias[s + SS];
#pragma unroll
        for (int g = 0; g < 8; g++) { off1 += red[g][s]; off2 += red[g][s + SS]; }

        const int so = (int)fminf(fmaxf(off1, 0.f), (float)(LL - 1));
        const int eo = (int)fminf(fmaxf(off2, 0.f), (float)(LL - 1));

        const int basei = s * LL;
        int start = basei + so;
        if (start > TT - LL) start = TT - LL;
        if (start < 0) start = 0;
        int end = basei + LL + eo;
        if (end < start) end = start;
        if (end > TT) end = TT;

        g_start[b * SS + s] = start;
        g_len[b * SS + s]   = end - start;
    }
}

// ---------------------------------------------------------------------------
// Kernel 3: vectorized gather+pad for one group of GB batches.
// grid = GB*SS*(LL/JC) = 1024 blocks, 192 threads.
// Reads should hit L2 (group input just streamed by k_pool, 50MB working set
// fits with 2.5x slack). 8 batched LDG.128, then 8 streaming stores (__stcs)
// so output lines self-victimize instead of evicting the group input.
// ---------------------------------------------------------------------------
__global__ __launch_bounds__(192) void k_gather(const float4* __restrict__ in,
                                                float4* __restrict__ out,
                                                int b0) {
    const int idx = blockIdx.x;
    const int jc = idx & (LL / JC - 1);          // 0..7
    const int s  = (idx >> 3) & (SS - 1);        // 0..31
    const int b  = b0 + (idx >> 8);              // group-local batch
    const int tid = threadIdx.x;                 // 0..191

    const int start = g_start[b * SS + s];
    const int len   = g_len[b * SS + s];

    const float4* src = in + ((size_t)b * TT + (size_t)start) * E4 + tid;
    float4* dst = out + ((size_t)(b * SS + s) * LL) * E4 + tid;

    const int j0 = jc * JC;
    float4 v[JC];
#pragma unroll
    for (int jj = 0; jj < JC; jj++) {
        const int j = j0 + jj;
        v[jj] = (j < len) ? src[(size_t)j * E4]
                          : make_float4(0.f, 0.f, 0.f, 0.f);
    }
#pragma unroll
    for (int jj = 0; jj < JC; jj++)
        __stcs(&dst[(size_t)(j0 + jj) * E4], v[jj]);
}

// ---------------------------------------------------------------------------
// Entry point. Inputs (metadata order): inputs f32 [B,T,E], W f32 [E,2S],
// b f32 [2S]. Output f32 [B,S,L,E].
// Pipeline: 4 groups of 4 batches; each group's gather re-reads its input
// while it is still L2-resident from that group's pool pass.
// ---------------------------------------------------------------------------
extern "C" void kernel_launch(void* const* d_in, const int* in_sizes, int n_in,
                              void* d_out, int out_size) {
    const float4* in  = (const float4*)d_in[0];
    const float* W    = (const float*)d_in[1];
    const float* bias = (const float*)d_in[2];
    float4* out       = (float4*)d_out;

    for (int b0 = 0; b0 < BB; b0 += GB) {
        k_pool<<<GB * NT, 192>>>(in, b0);
        k_idx<<<GB, 512>>>(W, bias, b0);
        k_gather<<<GB * SS * (LL / JC), 192>>>(in, out, b0);
    }
}

// round 15
// speedup vs baseline: 1.5661x; 1.5661x over previous
#include <cuda_runtime.h>
#include <cstddef>
#include <cstdint>

// Problem constants
#define BB 16      // batch
#define TT 2048    // text len
#define EE 768     // embed dim
#define E4 (EE/4)  // 192 float4 per row
#define SS 32      // num sentences
#define LL 64      // max sent len
#define NT 128     // t-chunks for pooling pass
#define TCH (TT / NT)   // 16 timesteps per chunk
#define JC 8       // rows (j) per gather block

// Scratch (no device allocation allowed -> __device__ globals)
__device__ float4 g_partial4[BB * NT * E4];  // 6.3MB partial sums (b, chunk, e4)
__device__ int    g_start[BB * SS];
__device__ int    g_len[BB * SS];

// 256-bit global ld/st. Plain load; store uses the .cs cache-op (streaming,
// evict-first) — the classic cache-op set is the only L2 control this ptxas
// accepts (both L2::evict_last ld.v4 and L2::no_allocate st were rejected).
struct F8 { uint32_t u[8]; };

__device__ __forceinline__ F8 ld256(const float* p) {
    F8 r;
    asm volatile("ld.global.v8.b32 {%0,%1,%2,%3,%4,%5,%6,%7}, [%8];"
                 : "=r"(r.u[0]), "=r"(r.u[1]), "=r"(r.u[2]), "=r"(r.u[3]),
                   "=r"(r.u[4]), "=r"(r.u[5]), "=r"(r.u[6]), "=r"(r.u[7])
                 : "l"(p));
    return r;
}

__device__ __forceinline__ void st256_cs(float* p, const F8& r) {
    asm volatile("st.global.cs.v8.b32 [%0], {%1,%2,%3,%4,%5,%6,%7,%8};"
                 :: "l"(p),
                    "r"(r.u[0]), "r"(r.u[1]), "r"(r.u[2]), "r"(r.u[3]),
                    "r"(r.u[4]), "r"(r.u[5]), "r"(r.u[6]), "r"(r.u[7])
                 : "memory");
}

// ---------------------------------------------------------------------------
// Kernel 1: streaming partial mean-pool over T (exact R10 measured-best).
// grid = BB*NT = 2048 blocks, 192 threads; thread owns one float4 column.
// TCH=16: 16 independent LDG.128 per thread, 4 accumulators.
// ---------------------------------------------------------------------------
__global__ __launch_bounds__(192) void k_pool(const float4* __restrict__ in) {
    const int blk = blockIdx.x;
    const int b = blk >> 7;          // / NT
    const int c = blk & (NT - 1);    // % NT
    const int e4 = threadIdx.x;      // 0..191

    const float4* base = in + ((size_t)b * TT + (size_t)c * TCH) * E4 + e4;

    float4 a0 = make_float4(0.f, 0.f, 0.f, 0.f);
    float4 a1 = make_float4(0.f, 0.f, 0.f, 0.f);
    float4 a2 = make_float4(0.f, 0.f, 0.f, 0.f);
    float4 a3 = make_float4(0.f, 0.f, 0.f, 0.f);
#pragma unroll
    for (int t = 0; t < TCH; t += 4) {
        float4 v0 = base[(size_t)(t + 0) * E4];
        float4 v1 = base[(size_t)(t + 1) * E4];
        float4 v2 = base[(size_t)(t + 2) * E4];
        float4 v3 = base[(size_t)(t + 3) * E4];
        a0.x += v0.x; a0.y += v0.y; a0.z += v0.z; a0.w += v0.w;
        a1.x += v1.x; a1.y += v1.y; a1.z += v1.z; a1.w += v1.w;
        a2.x += v2.x; a2.y += v2.y; a2.z += v2.z; a2.w += v2.w;
        a3.x += v3.x; a3.y += v3.y; a3.z += v3.z; a3.w += v3.w;
    }
    float4 s;
    s.x = (a0.x + a1.x) + (a2.x + a3.x);
    s.y = (a0.y + a1.y) + (a2.y + a3.y);
    s.z = (a0.z + a1.z) + (a2.z + a3.z);
    s.w = (a0.w + a1.w) + (a2.w + a3.w);
    g_partial4[(size_t)(b * NT + c) * E4 + e4] = s;
}

// ---------------------------------------------------------------------------
// Kernel 2: finish mean + tiny GEMV + exact index math (matches reference):
//   start_off = (int)clip(off_s, 0, 63); end_off = (int)clip(off_{s+32},0,63)
//   start = clip(s*64+start_off, 0, T-L); end = clip(s*64+64+end_off, start, T)
// grid = BB blocks, 512 threads (exact R10 version).
// ---------------------------------------------------------------------------
__global__ __launch_bounds__(512) void k_idx(const float* __restrict__ W,
                                             const float* __restrict__ bias) {
    const int b = blockIdx.x;
    const int tid = threadIdx.x;
    __shared__ float pooled[EE];
    __shared__ float4 pA[2 * E4];
    __shared__ float red[8][2 * SS];

    if (tid < 2 * E4) {
        const int g = tid / E4;          // 0..1 (chunk half)
        const int e4 = tid - g * E4;     // 0..191
        const float4* p = g_partial4 + ((size_t)b * NT + (size_t)g * (NT / 2)) * E4 + e4;
        float4 a0 = make_float4(0.f, 0.f, 0.f, 0.f);
        float4 a1 = make_float4(0.f, 0.f, 0.f, 0.f);
#pragma unroll 8
        for (int c = 0; c < NT / 2; c += 2) {
            float4 v0 = p[(size_t)c * E4];
            float4 v1 = p[(size_t)(c + 1) * E4];
            a0.x += v0.x; a0.y += v0.y; a0.z += v0.z; a0.w += v0.w;
            a1.x += v1.x; a1.y += v1.y; a1.z += v1.z; a1.w += v1.w;
        }
        float4 s;
        s.x = a0.x + a1.x; s.y = a0.y + a1.y; s.z = a0.z + a1.z; s.w = a0.w + a1.w;
        pA[tid] = s;
    }
    __syncthreads();
    if (tid < E4) {
        const float inv = 1.0f / (float)TT;
        float4 u = pA[tid], w = pA[E4 + tid];
        pooled[4 * tid + 0] = (u.x + w.x) * inv;
        pooled[4 * tid + 1] = (u.y + w.y) * inv;
        pooled[4 * tid + 2] = (u.z + w.z) * inv;
        pooled[4 * tid + 3] = (u.w + w.w) * inv;
    }
    __syncthreads();

    // col = tid & 63, segment g = tid >> 6 (0..7), 96 elems each.
    {
        const int col = tid & (2 * SS - 1);
        const int g = tid >> 6;
        float acc = 0.f;
        const int e0 = g * 96;
#pragma unroll 8
        for (int e = e0; e < e0 + 96; e++)
            acc = fmaf(pooled[e], W[e * (2 * SS) + col], acc);
        red[g][col] = acc;
    }
    __syncthreads();

    if (tid < SS) {
        const int s = tid;
        float off1 = bias[s], off2 = bias[s + SS];
#pragma unroll
        for (int g = 0; g < 8; g++) { off1 += red[g][s]; off2 += red[g][s + SS]; }

        const int so = (int)fminf(fmaxf(off1, 0.f), (float)(LL - 1));
        const int eo = (int)fminf(fmaxf(off2, 0.f), (float)(LL - 1));

        const int basei = s * LL;
        int start = basei + so;
        if (start > TT - LL) start = TT - LL;
        if (start < 0) start = 0;
        int end = basei + LL + eo;
        if (end < start) end = start;
        if (end > TT) end = TT;

        g_start[b * SS + s] = start;
        g_len[b * SS + s]   = end - start;
    }
}

// ---------------------------------------------------------------------------
// Kernel 3: gather+pad with 256-bit loads and 256-bit streaming stores.
// grid = BB*SS*(LL/JC) = 4096 blocks, 192 threads.
// Thread layout: half = tid/96 (row parity), c8 = tid%96 (32B chunk).
// Each thread: 4 rows (j0+half, +2, +4, +6), 4 independent LDG.256 batched
// before 4 STG.256.cs — half the LSU issues of the float4 version, same
// per-warp 1KB-contiguous coalescing.
// ---------------------------------------------------------------------------
__global__ __launch_bounds__(192) void k_gather(const float* __restrict__ in,
                                                float* __restrict__ out) {
    const int idx = blockIdx.x;
    const int jc = idx & (LL / JC - 1);          // 0..7
    const int s  = (idx >> 3) & (SS - 1);        // 0..31
    const int b  = idx >> 8;                     // 0..15
    const int tid = threadIdx.x;                 // 0..191
    const int half = tid / 96;                   // 0..1
    const int c8 = tid - half * 96;              // 0..95

    const int start = g_start[b * SS + s];
    const int len   = g_len[b * SS + s];

    const float* src = in + ((size_t)b * TT + (size_t)start) * EE + c8 * 8;
    float* dst = out + ((size_t)(b * SS + s) * LL) * EE + c8 * 8;

    const int j0 = jc * JC + half;               // rows j0, j0+2, j0+4, j0+6
    F8 v[4];
#pragma unroll
    for (int r = 0; r < 4; r++) {
        const int j = j0 + 2 * r;
        if (j < len) {
            v[r] = ld256(src + (size_t)j * EE);
        } else {
#pragma unroll
            for (int k = 0; k < 8; k++) v[r].u[k] = 0u;
        }
    }
#pragma unroll
    for (int r = 0; r < 4; r++)
        st256_cs(dst + (size_t)(j0 + 2 * r) * EE, v[r]);
}

// ---------------------------------------------------------------------------
// Entry point. Inputs (metadata order): inputs f32 [B,T,E], W f32 [E,2S],
// b f32 [2S]. Output f32 [B,S,L,E].
// ---------------------------------------------------------------------------
extern "C" void kernel_launch(void* const* d_in, const int* in_sizes, int n_in,
                              void* d_out, int out_size) {
    const float* in   = (const float*)d_in[0];
    const float* W    = (const float*)d_in[1];
    const float* bias = (const float*)d_in[2];
    float* out        = (float*)d_out;

    k_pool<<<BB * NT, 192>>>((const float4*)in);
    k_idx<<<BB, 512>>>(W, bias);
    k_gather<<<BB * SS * (LL / JC), 192>>>(in, out);
}

// round 16
// speedup vs baseline: 1.8681x; 1.1929x over previous
#include <cuda_runtime.h>
#include <cstddef>

// Problem constants
#define BB 16      // batch
#define TT 2048    // text len
#define EE 768     // embed dim
#define E4 (EE/4)  // 192 float4 per row
#define SS 32      // num sentences
#define LL 64      // max sent len
#define NT 128     // t-chunks for pooling pass
#define TCH (TT / NT)   // 16 timesteps per chunk

// Scratch (no device allocation allowed -> __device__ globals)
__device__ float4 g_partial4[BB * NT * E4];  // 6.3MB partial sums (b, chunk, e4)
__device__ int    g_start[BB * SS];
__device__ int    g_len[BB * SS];
__device__ int    g_dirty[BB * SS];          // sentence needs re-copy?

// ---------------------------------------------------------------------------
// Kernel 1: fused mean-pool + speculative identity copy.
// Because out[B,S,L,E] flattened == [B,T,E] when start==s*64 && len==64 (the
// overwhelmingly likely case: sigma(offset)~0.012, clip+trunc -> 0), we write
// each input row straight to out at the SAME linear offset while pooling.
// The rare displaced sentences are fixed afterwards by k_patch.
// grid = BB*NT = 2048 blocks, 192 threads; thread owns one float4 column.
// ---------------------------------------------------------------------------
__global__ __launch_bounds__(192) void k_pool_copy(const float4* __restrict__ in,
                                                   float4* __restrict__ out) {
    const int blk = blockIdx.x;
    const int b = blk >> 7;          // / NT
    const int c = blk & (NT - 1);    // % NT
    const int e4 = threadIdx.x;      // 0..191

    const size_t row0 = (size_t)b * TT + (size_t)c * TCH;
    const float4* src = in + row0 * E4 + e4;
    float4* dst = out + row0 * E4 + e4;   // identity layout: out == in rows

    float4 a0 = make_float4(0.f, 0.f, 0.f, 0.f);
    float4 a1 = make_float4(0.f, 0.f, 0.f, 0.f);
    float4 a2 = make_float4(0.f, 0.f, 0.f, 0.f);
    float4 a3 = make_float4(0.f, 0.f, 0.f, 0.f);
#pragma unroll
    for (int t = 0; t < TCH; t += 4) {
        float4 v0 = src[(size_t)(t + 0) * E4];
        float4 v1 = src[(size_t)(t + 1) * E4];
        float4 v2 = src[(size_t)(t + 2) * E4];
        float4 v3 = src[(size_t)(t + 3) * E4];
        a0.x += v0.x; a0.y += v0.y; a0.z += v0.z; a0.w += v0.w;
        a1.x += v1.x; a1.y += v1.y; a1.z += v1.z; a1.w += v1.w;
        a2.x += v2.x; a2.y += v2.y; a2.z += v2.z; a2.w += v2.w;
        a3.x += v3.x; a3.y += v3.y; a3.z += v3.z; a3.w += v3.w;
        __stcs(&dst[(size_t)(t + 0) * E4], v0);
        __stcs(&dst[(size_t)(t + 1) * E4], v1);
        __stcs(&dst[(size_t)(t + 2) * E4], v2);
        __stcs(&dst[(size_t)(t + 3) * E4], v3);
    }
    float4 s;
    s.x = (a0.x + a1.x) + (a2.x + a3.x);
    s.y = (a0.y + a1.y) + (a2.y + a3.y);
    s.z = (a0.z + a1.z) + (a2.z + a3.z);
    s.w = (a0.w + a1.w) + (a2.w + a3.w);
    g_partial4[(size_t)(b * NT + c) * E4 + e4] = s;
}

// ---------------------------------------------------------------------------
// Kernel 2: finish mean + tiny GEMV + exact index math (matches reference):
//   start_off = (int)clip(off_s, 0, 63); end_off = (int)clip(off_{s+32},0,63)
//   start = clip(s*64+start_off, 0, T-L); end = clip(s*64+64+end_off, start, T)
// Also flags sentences whose (start, len) differ from the speculative
// identity copy. grid = BB blocks, 512 threads.
// ---------------------------------------------------------------------------
__global__ __launch_bounds__(512) void k_idx(const float* __restrict__ W,
                                             const float* __restrict__ bias) {
    const int b = blockIdx.x;
    const int tid = threadIdx.x;
    __shared__ float pooled[EE];
    __shared__ float4 pA[2 * E4];
    __shared__ float red[8][2 * SS];

    if (tid < 2 * E4) {
        const int g = tid / E4;          // 0..1 (chunk half)
        const int e4 = tid - g * E4;     // 0..191
        const float4* p = g_partial4 + ((size_t)b * NT + (size_t)g * (NT / 2)) * E4 + e4;
        float4 a0 = make_float4(0.f, 0.f, 0.f, 0.f);
        float4 a1 = make_float4(0.f, 0.f, 0.f, 0.f);
#pragma unroll 8
        for (int c = 0; c < NT / 2; c += 2) {
            float4 v0 = p[(size_t)c * E4];
            float4 v1 = p[(size_t)(c + 1) * E4];
            a0.x += v0.x; a0.y += v0.y; a0.z += v0.z; a0.w += v0.w;
            a1.x += v1.x; a1.y += v1.y; a1.z += v1.z; a1.w += v1.w;
        }
        float4 s;
        s.x = a0.x + a1.x; s.y = a0.y + a1.y; s.z = a0.z + a1.z; s.w = a0.w + a1.w;
        pA[tid] = s;
    }
    __syncthreads();
    if (tid < E4) {
        const float inv = 1.0f / (float)TT;
        float4 u = pA[tid], w = pA[E4 + tid];
        pooled[4 * tid + 0] = (u.x + w.x) * inv;
        pooled[4 * tid + 1] = (u.y + w.y) * inv;
        pooled[4 * tid + 2] = (u.z + w.z) * inv;
        pooled[4 * tid + 3] = (u.w + w.w) * inv;
    }
    __syncthreads();

    // col = tid & 63, segment g = tid >> 6 (0..7), 96 elems each.
    {
        const int col = tid & (2 * SS - 1);
        const int g = tid >> 6;
        float acc = 0.f;
        const int e0 = g * 96;
#pragma unroll 8
        for (int e = e0; e < e0 + 96; e++)
            acc = fmaf(pooled[e], W[e * (2 * SS) + col], acc);
        red[g][col] = acc;
    }
    __syncthreads();

    if (tid < SS) {
        const int s = tid;
        float off1 = bias[s], off2 = bias[s + SS];
#pragma unroll
        for (int g = 0; g < 8; g++) { off1 += red[g][s]; off2 += red[g][s + SS]; }

        const int so = (int)fminf(fmaxf(off1, 0.f), (float)(LL - 1));
        const int eo = (int)fminf(fmaxf(off2, 0.f), (float)(LL - 1));

        const int basei = s * LL;
        int start = basei + so;
        if (start > TT - LL) start = TT - LL;
        if (start < 0) start = 0;
        int end = basei + LL + eo;
        if (end < start) end = start;
        if (end > TT) end = TT;

        const int len = end - start;
        g_start[b * SS + s] = start;
        g_len[b * SS + s]   = len;
        g_dirty[b * SS + s] = (start != basei) | (len != LL);
    }
}

// ---------------------------------------------------------------------------
// Kernel 3: patch pass. One block per sentence; early-exit when the
// speculative identity copy was already correct (the ~always case).
// Dirty sentences get fully rewritten: rows 0..len-1 gathered from start,
// rows len..63 zeroed. grid = BB*SS = 512 blocks, 192 threads.
// ---------------------------------------------------------------------------
__global__ __launch_bounds__(192) void k_patch(const float4* __restrict__ in,
                                               float4* __restrict__ out) {
    const int idx = blockIdx.x;
    const int s = idx & (SS - 1);
    const int b = idx >> 5;

    if (!g_dirty[b * SS + s]) return;

    const int tid = threadIdx.x;
    const int start = g_start[b * SS + s];
    const int len   = g_len[b * SS + s];

    const float4* src = in + ((size_t)b * TT + (size_t)start) * E4 + tid;
    float4* dst = out + ((size_t)(b * SS + s) * LL) * E4 + tid;

    for (int j = 0; j < LL; j++) {
        float4 v = (j < len) ? src[(size_t)j * E4]
                             : make_float4(0.f, 0.f, 0.f, 0.f);
        dst[(size_t)j * E4] = v;
    }
}

// ---------------------------------------------------------------------------
// Entry point. Inputs (metadata order): inputs f32 [B,T,E], W f32 [E,2S],
// b f32 [2S]. Output f32 [B,S,L,E].
// ---------------------------------------------------------------------------
extern "C" void kernel_launch(void* const* d_in, const int* in_sizes, int n_in,
                              void* d_out, int out_size) {
    const float4* in  = (const float4*)d_in[0];
    const float* W    = (const float*)d_in[1];
    const float* bias = (const float*)d_in[2];
    float4* out       = (float4*)d_out;

    k_pool_copy<<<BB * NT, 192>>>(in, out);
    k_idx<<<BB, 512>>>(W, bias);
    k_patch<<<BB * SS, 192>>>(in, out);
}